// round 2
// baseline (speedup 1.0000x reference)
#include <cuda_runtime.h>
#include <cstddef>

#define N_NODES 50000
#define N_EDGES 800000
#define EDGE_F  96
#define NODE_F  256
#define GLOB_F  64
#define HIDDEN  1024
#define MLP_IN  608    // NODE_F + 3*EDGE_F + GLOB_F
#define M_PAD   50048  // 391 * 128

// ---------------- scratch (static device globals; no allocation) ----------------
__device__ float        g_sum [N_NODES * EDGE_F];   // segment sum
__device__ unsigned int g_max [N_NODES * EDGE_F];   // segment max, order-mapped uint
__device__ float        g_cnt [N_NODES];            // segment count
__device__ float        g_H   [(size_t)M_PAD * MLP_IN];   // assembled MLP input
__device__ float        g_Hmid[(size_t)M_PAD * HIDDEN];   // hidden activations

// Order-preserving float<->uint mapping (monotone for all finite floats).
__device__ __forceinline__ unsigned int f2u_ord(float f) {
    unsigned int u = __float_as_uint(f);
    return (u & 0x80000000u) ? ~u : (u | 0x80000000u);
}
__device__ __forceinline__ float u2f_ord(unsigned int u) {
    unsigned int b = (u & 0x80000000u) ? (u ^ 0x80000000u) : ~u;
    return __uint_as_float(b);
}

// ---------------- init: zero accumulators + pad-row tails ----------------
__global__ void k_init() {
    int idx = blockIdx.x * blockDim.x + threadIdx.x;
    if (idx < N_NODES * EDGE_F) { g_sum[idx] = 0.0f; g_max[idx] = 0u; }
    if (idx < N_NODES) g_cnt[idx] = 0.0f;
    if (idx < (M_PAD - N_NODES) * MLP_IN)  g_H   [(size_t)N_NODES * MLP_IN + idx] = 0.0f;
    if (idx < (M_PAD - N_NODES) * HIDDEN)  g_Hmid[(size_t)N_NODES * HIDDEN + idx] = 0.0f;
}

// ---------------- edge scatter: sum + max + count ----------------
// One thread per (edge, 4-feature chunk): 800000 * 24 threads.
__global__ void k_scatter(const float* __restrict__ ea, const int* __restrict__ col) {
    int idx = blockIdx.x * blockDim.x + threadIdx.x;
    if (idx >= N_EDGES * 24) return;
    int e = idx / 24;
    int q = idx - e * 24;
    int dst = col[e];
    float4 v = *reinterpret_cast<const float4*>(ea + (size_t)e * EDGE_F + q * 4);

    float* s = g_sum + (size_t)dst * EDGE_F + q * 4;
    atomicAdd(s + 0, v.x);
    atomicAdd(s + 1, v.y);
    atomicAdd(s + 2, v.z);
    atomicAdd(s + 3, v.w);

    unsigned int* m = g_max + (size_t)dst * EDGE_F + q * 4;
    atomicMax(m + 0, f2u_ord(v.x));
    atomicMax(m + 1, f2u_ord(v.y));
    atomicMax(m + 2, f2u_ord(v.z));
    atomicMax(m + 3, f2u_ord(v.w));

    if (q == 0) atomicAdd(&g_cnt[dst], 1.0f);
}

// ---------------- assemble H = [x | sum | max | mean | u[batch]] ----------------
__global__ void k_assemble(const float* __restrict__ x,
                           const float* __restrict__ u,
                           const int*   __restrict__ batch) {
    int idx = blockIdx.x * blockDim.x + threadIdx.x;
    if (idx >= N_NODES * MLP_IN) return;
    int i = idx / MLP_IN;
    int f = idx - i * MLP_IN;
    float v;
    if (f < NODE_F) {
        v = x[(size_t)i * NODE_F + f];
    } else if (f < NODE_F + EDGE_F) {
        v = g_sum[(size_t)i * EDGE_F + (f - NODE_F)];
    } else if (f < NODE_F + 2 * EDGE_F) {
        float c = g_cnt[i];
        unsigned int mu = g_max[(size_t)i * EDGE_F + (f - NODE_F - EDGE_F)];
        v = (c > 0.0f) ? u2f_ord(mu) : 0.0f;
    } else if (f < NODE_F + 3 * EDGE_F) {
        float c = g_cnt[i];
        v = g_sum[(size_t)i * EDGE_F + (f - NODE_F - 2 * EDGE_F)] / fmaxf(c, 1.0f);
    } else {
        v = u[(size_t)batch[i] * GLOB_F + (f - NODE_F - 3 * EDGE_F)];
    }
    g_H[(size_t)idx] = v;
}

// ---------------- tiled fp32 SGEMM ----------------
// C[M,N] = A[M,K] @ B[K,N] (+ bias[N]) ; EPI==0: ReLU, store to C
//                                        EPI==1: + res[row*N+col], store to C
// BM=BN=128, BK=16, 256 threads, 8x8 per-thread tile. Grid y covers M_PAD
// (A rows padded & zeroed); stores guarded at real M.
template<int EPI>
__global__ __launch_bounds__(256) void k_sgemm(
    const float* __restrict__ A, const float* __restrict__ B,
    const float* __restrict__ bias, const float* __restrict__ res,
    float* __restrict__ C, int Mreal, int K, int N)
{
    constexpr int BM = 128, BN = 128, BK = 16, TM = 8, TN = 8;
    __shared__ float As[BK][BM];
    __shared__ float Bs[BK][BN];

    const int tid = threadIdx.x;
    const int bm  = blockIdx.y * BM;
    const int bn  = blockIdx.x * BN;
    const int tx  = tid & 15;     // 0..15
    const int ty  = tid >> 4;     // 0..15

    const int aRow = tid >> 2;          // 0..63
    const int aCol = (tid & 3) * 4;     // 0,4,8,12
    const int bRow = tid >> 5;          // 0..7
    const int bCol = (tid & 31) * 4;    // 0..124

    float acc[TM][TN] = {};

    for (int k0 = 0; k0 < K; k0 += BK) {
        #pragma unroll
        for (int r = 0; r < 2; r++) {
            float4 v = *reinterpret_cast<const float4*>(
                A + (size_t)(bm + aRow + r * 64) * K + k0 + aCol);
            As[aCol + 0][aRow + r * 64] = v.x;
            As[aCol + 1][aRow + r * 64] = v.y;
            As[aCol + 2][aRow + r * 64] = v.z;
            As[aCol + 3][aRow + r * 64] = v.w;
        }
        #pragma unroll
        for (int r = 0; r < 2; r++) {
            float4 v = *reinterpret_cast<const float4*>(
                B + (size_t)(k0 + bRow + r * 8) * N + bn + bCol);
            *reinterpret_cast<float4*>(&Bs[bRow + r * 8][bCol]) = v;
        }
        __syncthreads();

        #pragma unroll
        for (int kk = 0; kk < BK; kk++) {
            float ra[TM], rb[TN];
            #pragma unroll
            for (int i = 0; i < TM; i++) ra[i] = As[kk][ty * TM + i];
            #pragma unroll
            for (int j = 0; j < TN; j++) rb[j] = Bs[kk][tx * TN + j];
            #pragma unroll
            for (int i = 0; i < TM; i++)
                #pragma unroll
                for (int j = 0; j < TN; j++)
                    acc[i][j] = fmaf(ra[i], rb[j], acc[i][j]);
        }
        __syncthreads();
    }

    #pragma unroll
    for (int i = 0; i < TM; i++) {
        int row = bm + ty * TM + i;
        if (row >= Mreal) continue;
        #pragma unroll
        for (int j = 0; j < TN; j += 4) {
            int c0 = bn + tx * TN + j;
            float4 o;
            o.x = acc[i][j + 0] + bias[c0 + 0];
            o.y = acc[i][j + 1] + bias[c0 + 1];
            o.z = acc[i][j + 2] + bias[c0 + 2];
            o.w = acc[i][j + 3] + bias[c0 + 3];
            if (EPI == 0) {
                o.x = fmaxf(o.x, 0.0f); o.y = fmaxf(o.y, 0.0f);
                o.z = fmaxf(o.z, 0.0f); o.w = fmaxf(o.w, 0.0f);
            } else {
                const float4 r = *reinterpret_cast<const float4*>(
                    res + (size_t)row * N + c0);
                o.x += r.x; o.y += r.y; o.z += r.z; o.w += r.w;
            }
            *reinterpret_cast<float4*>(C + (size_t)row * N + c0) = o;
        }
    }
}

// ---------------- launch ----------------
extern "C" void kernel_launch(void* const* d_in, const int* in_sizes, int n_in,
                              void* d_out, int out_size) {
    const float* x          = (const float*)d_in[0];  // [50000, 256]
    const float* edge_attr  = (const float*)d_in[1];  // [800000, 96]
    const float* u          = (const float*)d_in[2];  // [8, 64]
    const float* W1         = (const float*)d_in[3];  // [608, 1024]
    const float* b1         = (const float*)d_in[4];  // [1024]
    const float* W2         = (const float*)d_in[5];  // [1024, 256]
    const float* b2         = (const float*)d_in[6];  // [256]
    const int*   edge_index = (const int*)  d_in[7];  // [2, 800000]
    const int*   batch      = (const int*)  d_in[8];  // [50000]
    float*       out        = (float*)d_out;          // [50000, 256]

    const int* col = edge_index + N_EDGES;  // destination row

    float* pH;    cudaGetSymbolAddress((void**)&pH,    g_H);
    float* pHmid; cudaGetSymbolAddress((void**)&pHmid, g_Hmid);

    // 1) init accumulators (+ zero pad tails)
    {
        int total = N_NODES * EDGE_F;  // 4.8M, covers all init work
        k_init<<<(total + 255) / 256, 256>>>();
    }
    // 2) edge scatter
    {
        int total = N_EDGES * 24;      // 19.2M
        k_scatter<<<(total + 255) / 256, 256>>>(edge_attr, col);
    }
    // 3) assemble H
    {
        int total = N_NODES * MLP_IN;  // 30.4M
        k_assemble<<<(total + 255) / 256, 256>>>(x, u, batch);
    }
    // 4) GEMM1: H[50048,608] @ W1[608,1024] + b1, ReLU -> Hmid
    {
        dim3 grid(HIDDEN / 128, M_PAD / 128);
        k_sgemm<0><<<grid, 256>>>(pH, W1, b1, nullptr, pHmid,
                                  N_NODES, MLP_IN, HIDDEN);
    }
    // 5) GEMM2: Hmid[50048,1024] @ W2[1024,256] + b2 + x -> out
    {
        dim3 grid(NODE_F / 128, M_PAD / 128);
        k_sgemm<1><<<grid, 256>>>(pHmid, W2, b2, x, out,
                                  N_NODES, HIDDEN, NODE_F);
    }
}

// round 8
// speedup vs baseline: 2.1564x; 2.1564x over previous
#include <cuda_runtime.h>
#include <cuda_bf16.h>
#include <cstdint>
#include <cstddef>

#define N_NODES 50000
#define N_EDGES 800000
#define EDGE_F  96
#define NODE_F  256
#define GLOB_F  64
#define HIDDEN  1024
#define MLP_IN  608     // NODE_F + 3*EDGE_F + GLOB_F
#define M_PAD   50048   // 391 * 128
#define KP1     1856    // 3*608 = 1824, padded to 29*64
#define KP2     3072    // 3*1024
#define NC1     (KP1/64)
#define NC2     (KP2/64)

// ---------------- scratch (static device globals; no allocation) ----------------
__device__ float         g_sum[N_NODES * EDGE_F];
__device__ unsigned int  g_max[N_NODES * EDGE_F];
__device__ float         g_cnt[N_NODES];
__device__ __nv_bfloat16 g_A1[(size_t)M_PAD * KP1];   // [hi|hi|lo] MLP input
__device__ __nv_bfloat16 g_B1[(size_t)HIDDEN * KP1];  // W1^T split [hi|lo|hi]
__device__ __nv_bfloat16 g_A2[(size_t)M_PAD * KP2];   // hidden acts [hi|hi|lo]
__device__ __nv_bfloat16 g_B2[(size_t)NODE_F * KP2];  // W2^T split [hi|lo|hi]

// ---------------- helpers ----------------
__device__ __forceinline__ uint32_t smem_u32(const void* p) {
    uint32_t a;
    asm("{ .reg .u64 t; cvta.to.shared.u64 t, %1; cvt.u32.u64 %0, t; }"
        : "=r"(a) : "l"(p));
    return a;
}
__device__ __forceinline__ unsigned int f2u_ord(float f) {
    unsigned int u = __float_as_uint(f);
    return (u & 0x80000000u) ? ~u : (u | 0x80000000u);
}
__device__ __forceinline__ float u2f_ord(unsigned int u) {
    unsigned int b = (u & 0x80000000u) ? (u ^ 0x80000000u) : ~u;
    return __uint_as_float(b);
}
__device__ __forceinline__ void bsplit(float v, __nv_bfloat16& hi, __nv_bfloat16& lo) {
    hi = __float2bfloat16(v);
    lo = __float2bfloat16(v - __bfloat162float(hi));
}

__device__ __forceinline__ void ldmx4(uint32_t& r0, uint32_t& r1, uint32_t& r2,
                                      uint32_t& r3, uint32_t addr) {
    asm volatile("ldmatrix.sync.aligned.m8n8.x4.shared.b16 {%0,%1,%2,%3}, [%4];"
                 : "=r"(r0), "=r"(r1), "=r"(r2), "=r"(r3) : "r"(addr));
}
__device__ __forceinline__ void mma16816(float* c, const uint32_t* a, const uint32_t* b) {
    asm volatile(
        "mma.sync.aligned.m16n8k16.row.col.f32.bf16.bf16.f32 "
        "{%0,%1,%2,%3}, {%4,%5,%6,%7}, {%8,%9}, {%0,%1,%2,%3};"
        : "+f"(c[0]), "+f"(c[1]), "+f"(c[2]), "+f"(c[3])
        : "r"(a[0]), "r"(a[1]), "r"(a[2]), "r"(a[3]), "r"(b[0]), "r"(b[1]));
}
#define CP_ASYNC16(dst, src) \
    asm volatile("cp.async.cg.shared.global [%0], [%1], 16;" :: "r"(dst), "l"(src))
#define CP_COMMIT() asm volatile("cp.async.commit_group;")

// ---------------- init: zero accumulators + pads ----------------
__global__ void k_init() {
    int idx = blockIdx.x * blockDim.x + threadIdx.x;
    if (idx < N_NODES * EDGE_F) { g_sum[idx] = 0.0f; g_max[idx] = 0u; }
    if (idx < N_NODES) g_cnt[idx] = 0.0f;
    if (idx < (M_PAD - N_NODES) * KP1)
        g_A1[(size_t)N_NODES * KP1 + idx] = __float2bfloat16(0.0f);
    if (idx < N_NODES * 32)
        g_A1[(size_t)(idx >> 5) * KP1 + 1824 + (idx & 31)] = __float2bfloat16(0.0f);
    if (idx < HIDDEN * 32)
        g_B1[(size_t)(idx >> 5) * KP1 + 1824 + (idx & 31)] = __float2bfloat16(0.0f);
}

// ---------------- edge scatter: sum + max + count ----------------
__global__ void k_scatter(const float* __restrict__ ea, const int* __restrict__ col) {
    int idx = blockIdx.x * blockDim.x + threadIdx.x;
    if (idx >= N_EDGES * 24) return;
    int e = idx / 24;
    int q = idx - e * 24;
    int dst = col[e];
    float4 v = *reinterpret_cast<const float4*>(ea + (size_t)e * EDGE_F + q * 4);

    float* s = g_sum + (size_t)dst * EDGE_F + q * 4;
    atomicAdd(s + 0, v.x); atomicAdd(s + 1, v.y);
    atomicAdd(s + 2, v.z); atomicAdd(s + 3, v.w);

    unsigned int* m = g_max + (size_t)dst * EDGE_F + q * 4;
    atomicMax(m + 0, f2u_ord(v.x)); atomicMax(m + 1, f2u_ord(v.y));
    atomicMax(m + 2, f2u_ord(v.z)); atomicMax(m + 3, f2u_ord(v.w));

    if (q == 0) atomicAdd(&g_cnt[dst], 1.0f);
}

// ---------------- assemble A1 = split([x | sum | max | mean | u[batch]]) ----------------
__global__ void k_assemble(const float* __restrict__ x,
                           const float* __restrict__ u,
                           const int*   __restrict__ batch) {
    int idx = blockIdx.x * blockDim.x + threadIdx.x;
    if (idx >= N_NODES * MLP_IN) return;
    int i = idx / MLP_IN;
    int f = idx - i * MLP_IN;
    float v;
    if (f < NODE_F) {
        v = x[(size_t)i * NODE_F + f];
    } else if (f < NODE_F + EDGE_F) {
        v = g_sum[(size_t)i * EDGE_F + (f - NODE_F)];
    } else if (f < NODE_F + 2 * EDGE_F) {
        float c = g_cnt[i];
        unsigned int mu = g_max[(size_t)i * EDGE_F + (f - NODE_F - EDGE_F)];
        v = (c > 0.0f) ? u2f_ord(mu) : 0.0f;
    } else if (f < NODE_F + 3 * EDGE_F) {
        float c = g_cnt[i];
        v = g_sum[(size_t)i * EDGE_F + (f - NODE_F - 2 * EDGE_F)] / fmaxf(c, 1.0f);
    } else {
        v = u[(size_t)batch[i] * GLOB_F + (f - NODE_F - 3 * EDGE_F)];
    }
    __nv_bfloat16 hi, lo; bsplit(v, hi, lo);
    __nv_bfloat16* row = g_A1 + (size_t)i * KP1;
    row[f] = hi; row[608 + f] = hi; row[1216 + f] = lo;   // A segments [hi|hi|lo]
}

// ---------------- weight transpose + split ----------------
__global__ void k_w1(const float* __restrict__ W1) {
    int idx = blockIdx.x * blockDim.x + threadIdx.x;
    if (idx >= MLP_IN * HIDDEN) return;
    int k = idx / HIDDEN, n = idx - k * HIDDEN;
    __nv_bfloat16 hi, lo; bsplit(W1[idx], hi, lo);
    __nv_bfloat16* row = g_B1 + (size_t)n * KP1;
    row[k] = hi; row[608 + k] = lo; row[1216 + k] = hi;
}
__global__ void k_w2(const float* __restrict__ W2) {
    int idx = blockIdx.x * blockDim.x + threadIdx.x;
    if (idx >= HIDDEN * NODE_F) return;
    int k = idx / NODE_F, n = idx - k * NODE_F;
    __nv_bfloat16 hi, lo; bsplit(W2[idx], hi, lo);
    __nv_bfloat16* row = g_B2 + (size_t)n * KP2;
    row[k] = hi; row[1024 + k] = lo; row[2048 + k] = hi;
}

// ---------------- HMMA bf16 GEMM: C[128,128] tile = A[128,K'] @ B[128,K']^T ----------------
// A, B row-major with K contiguous (B holds B^T rows). SW128-swizzled smem tiles,
// cp.async double buffer, 8 warps each 64x32 via m16n8k16.
// EPI==0: h = relu(D + b1); store hi/hi/lo triple into g_A2
// EPI==1: out[row] = D + b2 + x[row], guarded row < N_NODES
#define SMEM_BYTES 65536

template <int EPI>
__global__ __launch_bounds__(256, 2) void k_mma(
    const __nv_bfloat16* __restrict__ A, const __nv_bfloat16* __restrict__ B,
    const float* __restrict__ bias, const float* __restrict__ res,
    float* __restrict__ outp, int K, int NC)
{
    extern __shared__ char smem[];
    const uint32_t smb = smem_u32(smem);
    const int tid  = threadIdx.x;
    const int wid  = tid >> 5;
    const int lane = tid & 31;
    const int wy = wid & 1;        // 2 warp-rows of 64
    const int wx = wid >> 1;       // 4 warp-cols of 32
    const size_t bm = (size_t)blockIdx.y * 128;
    const int bn = blockIdx.x * 128;

    // per-thread cp.async mapping (shared by A and B tiles)
    int lr[4], ljs[4];
    #pragma unroll
    for (int t = 0; t < 4; t++) {
        int idx = tid + t * 256;
        lr[t]  = idx >> 3;                       // row 0..127
        int j  = idx & 7;                        // 16B chunk 0..7
        ljs[t] = j;
    }

    float acc[4][4][4];
    #pragma unroll
    for (int i = 0; i < 4; i++)
        #pragma unroll
        for (int j = 0; j < 4; j++)
            #pragma unroll
            for (int q = 0; q < 4; q++) acc[i][j][q] = 0.0f;

    // ldmatrix lane constants
    const int rA  = wy * 64 + (lane & 7) + ((lane >> 3) & 1) * 8;
    const int jA  = lane >> 4;            // 0/1 = k chunk half
    const int sA  = rA & 7;
    const int rB  = wx * 32 + (lane & 7) + ((lane >> 4) & 1) * 8;
    const int jB  = (lane >> 3) & 1;
    const int sB  = rB & 7;

    #define LOAD_CHUNK(cc, bb) do {                                              \
        uint32_t dA_ = smb + (bb) * 16384;                                       \
        uint32_t dB_ = smb + 32768 + (bb) * 16384;                               \
        int k0_ = (cc) * 64;                                                     \
        _Pragma("unroll")                                                        \
        for (int t_ = 0; t_ < 4; t_++) {                                         \
            int r_ = lr[t_], j_ = ljs[t_];                                       \
            uint32_t off_ = (uint32_t)(r_ * 128 + ((j_ ^ (r_ & 7)) << 4));       \
            const __nv_bfloat16* ga_ = A + (bm + r_) * (size_t)K + k0_ + j_ * 8; \
            const __nv_bfloat16* gb_ = B + ((size_t)(bn + r_)) * (size_t)K + k0_ + j_ * 8; \
            CP_ASYNC16(dA_ + off_, ga_);                                         \
            CP_ASYNC16(dB_ + off_, gb_);                                         \
        }                                                                        \
        CP_COMMIT();                                                             \
    } while (0)

    LOAD_CHUNK(0, 0);

    for (int c = 0; c < NC; c++) {
        int b = c & 1;
        if (c + 1 < NC) {
            LOAD_CHUNK(c + 1, b ^ 1);
            asm volatile("cp.async.wait_group 1;");
        } else {
            asm volatile("cp.async.wait_group 0;");
        }
        __syncthreads();

        uint32_t baseA = smb + b * 16384;
        uint32_t baseB = smb + 32768 + b * 16384;
        #pragma unroll
        for (int ks = 0; ks < 4; ks++) {
            uint32_t af[4][4], bf[2][4];
            #pragma unroll
            for (int mt = 0; mt < 4; mt++) {
                uint32_t addr = baseA + rA * 128 + mt * 2048
                              + (uint32_t)(((ks * 2 + jA) ^ sA) << 4);
                ldmx4(af[mt][0], af[mt][1], af[mt][2], af[mt][3], addr);
            }
            #pragma unroll
            for (int p = 0; p < 2; p++) {
                uint32_t addr = baseB + rB * 128 + p * 2048
                              + (uint32_t)(((ks * 2 + jB) ^ sB) << 4);
                ldmx4(bf[p][0], bf[p][1], bf[p][2], bf[p][3], addr);
            }
            #pragma unroll
            for (int mt = 0; mt < 4; mt++)
                #pragma unroll
                for (int nt = 0; nt < 4; nt++) {
                    uint32_t bb[2] = { bf[nt >> 1][(nt & 1) * 2],
                                       bf[nt >> 1][(nt & 1) * 2 + 1] };
                    mma16816(acc[mt][nt], af[mt], bb);
                }
        }
        __syncthreads();
    }

    // ---------------- epilogue ----------------
    const int g   = lane >> 2;
    const int tig = lane & 3;
    #pragma unroll
    for (int mt = 0; mt < 4; mt++) {
        #pragma unroll
        for (int nt = 0; nt < 4; nt++) {
            int row0 = (int)bm + wy * 64 + mt * 16 + g;
            int col0 = bn + wx * 32 + nt * 8 + 2 * tig;
            float bv0 = bias[col0], bv1 = bias[col0 + 1];
            float c0 = acc[mt][nt][0] + bv0;
            float c1 = acc[mt][nt][1] + bv1;
            float c2 = acc[mt][nt][2] + bv0;
            float c3 = acc[mt][nt][3] + bv1;
            if (EPI == 0) {
                c0 = fmaxf(c0, 0.0f); c1 = fmaxf(c1, 0.0f);
                c2 = fmaxf(c2, 0.0f); c3 = fmaxf(c3, 0.0f);
                __nv_bfloat16 h0, l0, h1, l1;
                // pair (row0): c0,c1
                bsplit(c0, h0, l0); bsplit(c1, h1, l1);
                __nv_bfloat162 hv; hv.x = h0; hv.y = h1;
                __nv_bfloat162 lv; lv.x = l0; lv.y = l1;
                __nv_bfloat16* rp = g_A2 + (size_t)row0 * KP2;
                *reinterpret_cast<__nv_bfloat162*>(rp + col0)        = hv;
                *reinterpret_cast<__nv_bfloat162*>(rp + 1024 + col0) = hv;
                *reinterpret_cast<__nv_bfloat162*>(rp + 2048 + col0) = lv;
                // pair (row0+8): c2,c3
                bsplit(c2, h0, l0); bsplit(c3, h1, l1);
                hv.x = h0; hv.y = h1; lv.x = l0; lv.y = l1;
                rp += (size_t)8 * KP2;
                *reinterpret_cast<__nv_bfloat162*>(rp + col0)        = hv;
                *reinterpret_cast<__nv_bfloat162*>(rp + 1024 + col0) = hv;
                *reinterpret_cast<__nv_bfloat162*>(rp + 2048 + col0) = lv;
            } else {
                if (row0 < N_NODES) {
                    float2 xv = *reinterpret_cast<const float2*>(
                        res + (size_t)row0 * NODE_F + col0);
                    float2 o = make_float2(c0 + xv.x, c1 + xv.y);
                    *reinterpret_cast<float2*>(outp + (size_t)row0 * NODE_F + col0) = o;
                }
                int row1 = row0 + 8;
                if (row1 < N_NODES) {
                    float2 xv = *reinterpret_cast<const float2*>(
                        res + (size_t)row1 * NODE_F + col0);
                    float2 o = make_float2(c2 + xv.x, c3 + xv.y);
                    *reinterpret_cast<float2*>(outp + (size_t)row1 * NODE_F + col0) = o;
                }
            }
        }
    }
}

// ---------------- launch ----------------
extern "C" void kernel_launch(void* const* d_in, const int* in_sizes, int n_in,
                              void* d_out, int out_size) {
    const float* x          = (const float*)d_in[0];
    const float* edge_attr  = (const float*)d_in[1];
    const float* u          = (const float*)d_in[2];
    const float* W1         = (const float*)d_in[3];
    const float* b1         = (const float*)d_in[4];
    const float* W2         = (const float*)d_in[5];
    const float* b2         = (const float*)d_in[6];
    const int*   edge_index = (const int*)  d_in[7];
    const int*   batch      = (const int*)  d_in[8];
    float*       out        = (float*)d_out;

    const int* col = edge_index + N_EDGES;

    __nv_bfloat16 *pA1, *pB1, *pA2, *pB2;
    cudaGetSymbolAddress((void**)&pA1, g_A1);
    cudaGetSymbolAddress((void**)&pB1, g_B1);
    cudaGetSymbolAddress((void**)&pA2, g_A2);
    cudaGetSymbolAddress((void**)&pB2, g_B2);

    cudaFuncSetAttribute(k_mma<0>, cudaFuncAttributeMaxDynamicSharedMemorySize, SMEM_BYTES);
    cudaFuncSetAttribute(k_mma<1>, cudaFuncAttributeMaxDynamicSharedMemorySize, SMEM_BYTES);

    // 1) init
    {
        int total = N_NODES * EDGE_F;
        k_init<<<(total + 255) / 256, 256>>>();
    }
    // 2) weight transpose+split
    k_w1<<<(MLP_IN * HIDDEN + 255) / 256, 256>>>(W1);
    k_w2<<<(HIDDEN * NODE_F + 255) / 256, 256>>>(W2);
    // 3) edge scatter
    {
        int total = N_EDGES * 24;
        k_scatter<<<(total + 255) / 256, 256>>>(edge_attr, col);
    }
    // 4) assemble A1 (bf16 split)
    {
        int total = N_NODES * MLP_IN;
        k_assemble<<<(total + 255) / 256, 256>>>(x, u, batch);
    }
    // 5) GEMM1: A1[50048,1856] @ B1^T -> relu(+b1) -> g_A2 (bf16 triple)
    {
        dim3 grid(HIDDEN / 128, M_PAD / 128);
        k_mma<0><<<grid, 256, SMEM_BYTES>>>(pA1, pB1, b1, nullptr, nullptr, KP1, NC1);
    }
    // 6) GEMM2: A2[50048,3072] @ B2^T + b2 + x -> out
    {
        dim3 grid(NODE_F / 128, M_PAD / 128);
        k_mma<1><<<grid, 256, SMEM_BYTES>>>(pA2, pB2, b2, x, out, KP2, NC2);
    }
}